// round 13
// baseline (speedup 1.0000x reference)
#include <cuda_runtime.h>
#include <cuda_bf16.h>
#include <cstdint>

// ---------------------------------------------------------------------------
// GlobalMatchingTokenizer: 3 levels of efficient global matching attention.
// B=2, C={64,128,192}, H=W={64,32,16}, N=H*W, TOKEN_DIM=192, NUM_HEADS=4,
// HEAD_DIM=48, TOPK=128.
// Round 13: R11 launch structure (levels whole, 3-stream fork-join).
// attn: 1024-bin (10-bit) first histogram + CAP=512 direct rank -> the
// refinement sweep almost never fires (2 full sweeps instead of 3).
// ---------------------------------------------------------------------------

#define NH 4
#define HD 48
#define TD 192
#define KSEL 128
#define TN 16
#define CAP 512
#define SPAD 52

// Scratch (device globals; per-level disjoint offsets for stream overlap).
__device__ float g_S[143130624];
__device__ float g_Q[1990656];
__device__ float g_K[1990656];
__device__ float g_V[1990656];
__device__ float g_O[1990656];

// ---------------------------------------------------------------------------
// Kernel 1: QKV projection + positional encoding, n-tiled for weight reuse.
// grid = B*(N/TN), 384 threads.
// ---------------------------------------------------------------------------
__global__ void proj_kernel(const float* __restrict__ f1,
                            const float* __restrict__ f2,
                            const float* __restrict__ qw, const float* __restrict__ qb,
                            const float* __restrict__ kw, const float* __restrict__ kb,
                            const float* __restrict__ vw, const float* __restrict__ vb,
                            int C, int N, int W, size_t qoff)
{
    __shared__ float s1[TD][TN];
    __shared__ float s2[TD][TN];
    const int tid  = threadIdx.x;
    const int t    = tid % TD;
    const int half = tid / TD;
    const int nt = N / TN;
    const int n0 = (blockIdx.x % nt) * TN;
    const int b  = blockIdx.x / nt;

    for (int i = tid; i < C * TN; i += 384) {
        const int c = i / TN, j = i % TN;
        s1[c][j] = f1[((size_t)b * C + c) * N + n0 + j];
        s2[c][j] = f2[((size_t)b * C + c) * N + n0 + j];
    }
    __syncthreads();

    const int j0 = half * (TN / 2);
    float aq[TN / 2], ak[TN / 2], av[TN / 2];
    const float bq = qb[t], bk = kb[t], bv = vb[t];
    #pragma unroll
    for (int j = 0; j < TN / 2; ++j) { aq[j] = bq; ak[j] = bk; av[j] = bv; }

    for (int c = 0; c < C; ++c) {
        const float wq = qw[c * TD + t];
        const float wk = kw[c * TD + t];
        const float wv = vw[c * TD + t];
        #pragma unroll
        for (int j = 0; j < TN / 2; ++j) {
            const float a1 = s1[c][j0 + j];
            const float a2 = s2[c][j0 + j];
            aq[j] = fmaf(a1, wq, aq[j]);
            ak[j] = fmaf(a2, wk, ak[j]);
            av[j] = fmaf(a2, wv, av[j]);
        }
    }

    const float step = -9.210340371976184f / 96.0f;  // -ln(10000)/96
    const float div  = expf(step * (float)(t < 96 ? t : t - 96));
    #pragma unroll
    for (int j = 0; j < TN / 2; ++j) {
        const int n = n0 + j0 + j;
        const float pe = (t < 96) ? sinf((float)(n % W) * div)
                                  : cosf((float)(n / W) * div);
        aq[j] += pe;
        ak[j] += pe;
    }

    const int h = t / HD;
    const int d = t % HD;
    const size_t base = qoff + (((size_t)b * NH + h) * N + n0 + j0) * HD + d;
    #pragma unroll
    for (int j = 0; j < TN / 2; ++j) {
        g_Q[base + (size_t)j * HD] = aq[j];
        g_K[base + (size_t)j * HD] = ak[j];
        g_V[base + (size_t)j * HD] = av[j];
    }
}

// ---------------------------------------------------------------------------
// Kernel 2: scores GEMM (fp32 FFMA). S[bh][n][m] = scale*dot(Q[n],K[m]).
// grid = (N/128, N/128, B*NH), 256 threads, 8x8 per thread, interleaved.
// ---------------------------------------------------------------------------
__global__ void __launch_bounds__(256) scores_kernel(int N, size_t soff, size_t qoff)
{
    __shared__ float Qs[128][SPAD];
    __shared__ float Ks[128][SPAD];

    const int bh = blockIdx.z;
    const float* __restrict__ Qb = g_Q + qoff + (size_t)bh * N * HD;
    const float* __restrict__ Kb = g_K + qoff + (size_t)bh * N * HD;
    float* __restrict__ Sb = g_S + soff + (size_t)bh * N * N;

    const int tid = threadIdx.x;
    const int rb = blockIdx.y * 128;
    const int cb = blockIdx.x * 128;

    for (int i = tid; i < 128 * 12; i += 256) {
        const int r = i / 12, q = (i % 12) * 4;
        *(float4*)&Qs[r][q] = *(const float4*)(Qb + (size_t)(rb + r) * HD + q);
        *(float4*)&Ks[r][q] = *(const float4*)(Kb + (size_t)(cb + r) * HD + q);
    }
    __syncthreads();

    const int ty = tid >> 4, tx = tid & 15;
    float acc[8][8] = {};

    #pragma unroll
    for (int kk = 0; kk < HD; kk += 2) {
        float2 qv[8], kv[8];
        #pragma unroll
        for (int i = 0; i < 8; ++i) {
            qv[i] = *(const float2*)&Qs[ty + 16 * i][kk];
            kv[i] = *(const float2*)&Ks[tx + 16 * i][kk];
        }
        #pragma unroll
        for (int i = 0; i < 8; ++i)
            #pragma unroll
            for (int j = 0; j < 8; ++j) {
                acc[i][j] = fmaf(qv[i].x, kv[j].x, acc[i][j]);
                acc[i][j] = fmaf(qv[i].y, kv[j].y, acc[i][j]);
            }
    }

    const float scale = 0.14433756729740643f;  // 1/sqrt(48)
    #pragma unroll
    for (int i = 0; i < 8; ++i) {
        const size_t ro = (size_t)(rb + ty + 16 * i) * N + cb + tx;
        #pragma unroll
        for (int j = 0; j < 8; ++j)
            Sb[ro + 16 * j] = acc[i][j] * scale;
    }
}

// ---------------------------------------------------------------------------
// Kernel 3: exact top-128 per row. 10-bit (1024-bin) first histogram;
// parallel bin pick; gather (plain predicated atomics) + direct exact rank
// (CAP=512); full-sweep refinement only as rare fallback; atomic-free Z/V.
// grid = B*NH*N rows, 256 threads. CHN = N/1024 uint4 chunks; GUARD: N<1024.
// ---------------------------------------------------------------------------
__device__ __forceinline__ unsigned int floatToKey(float f)
{
    unsigned int u = __float_as_uint(f);
    return (u & 0x80000000u) ? ~u : (u | 0x80000000u);
}
__device__ __forceinline__ float keyToFloat(unsigned int u)
{
    unsigned int b = (u & 0x80000000u) ? (u & 0x7fffffffu) : ~u;
    return __uint_as_float(b);
}

// Parallel bin pick over 256*BPT bins. After internal barrier:
// s_bin = selected bin, s_need = remaining need inside bin, s_cand = bin count.
template <int BPT>
__device__ __forceinline__ void pick_bin(const unsigned int* hist,
                                         int tid, int wid, int lane,
                                         int* wsum, int* s_need,
                                         unsigned int* s_bin, int* s_cand)
{
    unsigned int hv[BPT];
    if (BPT == 1) {
        hv[0] = hist[tid];
    } else {
        #pragma unroll
        for (int q = 0; q < BPT / 4; ++q) {
            const uint4 h4 = ((const uint4*)hist)[tid * (BPT / 4) + q];
            hv[4 * q + 0] = h4.x; hv[4 * q + 1] = h4.y;
            hv[4 * q + 2] = h4.z; hv[4 * q + 3] = h4.w;
        }
    }
    int tsum = 0;
    #pragma unroll
    for (int b = 0; b < BPT; ++b) tsum += (int)hv[b];
    int x = tsum;                                    // inclusive suffix in warp
    #pragma unroll
    for (int off = 1; off < 32; off <<= 1) {
        const int y = __shfl_down_sync(0xffffffffu, x, off);
        if (lane + off < 32) x += y;
    }
    if (lane == 0) wsum[wid] = x;
    const int need = *s_need;
    __syncthreads();
    int above = x - tsum;                            // strictly above this thread
    for (int w = wid + 1; w < 8; ++w) above += wsum[w];
    if (above < need && above + tsum >= need) {
        int cum = above;
        #pragma unroll
        for (int b = BPT - 1; b >= 0; --b) {
            cum += (int)hv[b];
            if (cum >= need) {
                *s_bin  = (unsigned int)(tid * BPT + b);
                *s_need = need - (cum - (int)hv[b]);
                *s_cand = (int)hv[b];
                break;
            }
        }
    }
    __syncthreads();
}

template <int CHN, bool GUARD>
__global__ void __launch_bounds__(256) attn_kernel(int N, size_t soff, size_t qoff)
{
    extern __shared__ unsigned int keys[];        // N keys (dynamic)
    __shared__ unsigned int hist[1024];
    __shared__ __align__(16) unsigned int ckey[CAP];
    __shared__ int          cidx[CAP];
    __shared__ float        wl[KSEL];
    __shared__ int          ml[KSEL];
    __shared__ float        accs2[4][HD];
    __shared__ int          wsum[8];
    __shared__ unsigned int uwred[8];
    __shared__ float        fwred[4];
    __shared__ int          s_need, s_cand, s_cnt, s_ccnt;
    __shared__ unsigned int s_bin;

    const int tid  = threadIdx.x;
    const int wid  = tid >> 5, lane = tid & 31;
    const size_t row = blockIdx.x;
    const float* __restrict__ Srow = g_S + soff + row * (size_t)N;
    const int nv4 = N >> 2;

    ((uint4*)hist)[tid] = make_uint4(0u, 0u, 0u, 0u);   // 1024 bins
    if (tid == 0) { s_need = KSEL; s_cnt = 0; s_ccnt = 0; }
    __syncthreads();

    // Sweep 1: uint4 load + key conversion + smem store + 10-bit histogram.
    unsigned int lmax = 0u;
    #pragma unroll
    for (int c = 0; c < CHN; ++c) {
        const int v4 = tid + 256 * c;
        if (!GUARD || v4 < nv4) {
            const float4 f = ((const float4*)Srow)[v4];
            uint4 k;
            k.x = floatToKey(f.x); k.y = floatToKey(f.y);
            k.z = floatToKey(f.z); k.w = floatToKey(f.w);
            ((uint4*)keys)[v4] = k;
            atomicAdd(&hist[k.x >> 22], 1u);
            atomicAdd(&hist[k.y >> 22], 1u);
            atomicAdd(&hist[k.z >> 22], 1u);
            atomicAdd(&hist[k.w >> 22], 1u);
            lmax = max(lmax, max(max(k.x, k.y), max(k.z, k.w)));
        }
    }
    #pragma unroll
    for (int off = 16; off; off >>= 1)
        lmax = max(lmax, __shfl_down_sync(0xffffffffu, lmax, off));
    if (lane == 0) uwred[wid] = lmax;
    __syncthreads();
    unsigned int mk = uwred[0];
    #pragma unroll
    for (int w = 1; w < 8; ++w) mk = max(mk, uwred[w]);
    const float smax = keyToFloat(mk);

    // Pick over 1024 bins (bits 31..22).
    pick_bin<4>(hist, tid, wid, lane, wsum, &s_need, &s_bin, &s_cand);

    int sh = 22;
    unsigned int pfx = s_bin;
    int cand = s_cand;

    // RARE fallback refinement: selected bin still holds > CAP keys.
    while (cand > CAP && sh > 0) {
        const int width = (sh >= 8) ? 8 : sh;
        const int nsh = sh - width;
        const unsigned int mask = (1u << width) - 1u;
        if (tid < 256) hist[tid] = 0u;
        __syncthreads();
        #pragma unroll
        for (int c = 0; c < CHN; ++c) {
            const int v4 = tid + 256 * c;
            if (!GUARD || v4 < nv4) {
                const uint4 k = ((const uint4*)keys)[v4];
                const unsigned int kk[4] = {k.x, k.y, k.z, k.w};
                #pragma unroll
                for (int e = 0; e < 4; ++e)
                    if ((kk[e] >> sh) == pfx)
                        atomicAdd(&hist[(kk[e] >> nsh) & mask], 1u);
            }
        }
        __syncthreads();
        pick_bin<1>(hist, tid, wid, lane, wsum, &s_need, &s_bin, &s_cand);
        pfx = (pfx << width) | s_bin;
        cand = s_cand;
        sh = nsh;
    }

    const int needC = s_need;

    if (cand <= CAP) {
        // Sweep 2: winners (> bin) and candidates (== bin), plain atomics.
        #pragma unroll
        for (int c = 0; c < CHN; ++c) {
            const int v4 = tid + 256 * c;
            if (!GUARD || v4 < nv4) {
                const uint4 k = ((const uint4*)keys)[v4];
                const unsigned int kk[4] = {k.x, k.y, k.z, k.w};
                #pragma unroll
                for (int e = 0; e < 4; ++e) {
                    const unsigned int ub = kk[e] >> sh;
                    if (ub > pfx) {
                        const int slot = atomicAdd(&s_cnt, 1);
                        wl[slot] = __expf(keyToFloat(kk[e]) - smax);
                        ml[slot] = 4 * v4 + e;
                    } else if (ub == pfx) {
                        const int slot = atomicAdd(&s_ccnt, 1);
                        ckey[slot] = kk[e];
                        cidx[slot] = 4 * v4 + e;
                    }
                }
            }
        }
        __syncthreads();

        // Direct exact rank among candidates (key desc, index asc).
        const int cc = s_ccnt;           // == cand, in (0, CAP]
        for (int i = tid; i < cc; i += 256) {
            const unsigned int ki = ckey[i];
            const int idi = cidx[i];
            int r = 0;
            for (int j0 = 0; j0 < cc; j0 += 4) {
                const uint4 k4 = *(const uint4*)&ckey[j0];
                if (j0 + 0 < cc) { if (k4.x > ki || (k4.x == ki && cidx[j0 + 0] < idi)) ++r; }
                if (j0 + 1 < cc) { if (k4.y > ki || (k4.y == ki && cidx[j0 + 1] < idi)) ++r; }
                if (j0 + 2 < cc) { if (k4.z > ki || (k4.z == ki && cidx[j0 + 2] < idi)) ++r; }
                if (j0 + 3 < cc) { if (k4.w > ki || (k4.w == ki && cidx[j0 + 3] < idi)) ++r; }
            }
            if (r < needC) {
                const int slot = atomicAdd(&s_cnt, 1);
                wl[slot] = __expf(keyToFloat(ki) - smax);
                ml[slot] = idi;
            }
        }
    } else {
        // Pathological: > CAP keys equal on all 32 bits (sh == 0, pfx == key).
        #pragma unroll
        for (int c = 0; c < CHN; ++c) {
            const int v4 = tid + 256 * c;
            if (!GUARD || v4 < nv4) {
                const uint4 k = ((const uint4*)keys)[v4];
                const unsigned int kk[4] = {k.x, k.y, k.z, k.w};
                #pragma unroll
                for (int e = 0; e < 4; ++e) {
                    if (kk[e] > pfx) {
                        const int slot = atomicAdd(&s_cnt, 1);
                        wl[slot] = __expf(keyToFloat(kk[e]) - smax);
                        ml[slot] = 4 * v4 + e;
                    }
                }
            }
        }
        __syncthreads();
        const int baseCnt = s_cnt;
        const int need = KSEL - baseCnt;
        const float wtie = __expf(keyToFloat(pfx) - smax);
        #pragma unroll
        for (int c = 0; c < CHN; ++c) {
            const int v4 = tid + 256 * c;
            if (!GUARD || v4 < nv4) {
                const uint4 k = ((const uint4*)keys)[v4];
                const unsigned int kk[4] = {k.x, k.y, k.z, k.w};
                #pragma unroll
                for (int e = 0; e < 4; ++e) {
                    if (kk[e] == pfx) {
                        const int idx = 4 * v4 + e;
                        int r = 0;
                        for (int j = 0; j < idx && r < need; ++j)
                            r += (keys[j] == pfx);
                        if (r < need) {
                            wl[baseCnt + r] = wtie;
                            ml[baseCnt + r] = idx;
                        }
                    }
                }
            }
        }
    }
    __syncthreads();   // all KSEL slots of wl/ml final

    // Z (shuffle + per-warp partials) and V accumulation, atomic-free.
    float z = (tid < KSEL) ? wl[tid] : 0.f;
    #pragma unroll
    for (int off = 16; off; off >>= 1)
        z += __shfl_down_sync(0xffffffffu, z, off);
    if (lane == 0 && wid < 4) fwred[wid] = z;

    const size_t bh = row / (size_t)N;
    const float* __restrict__ Vb = g_V + qoff + bh * (size_t)N * HD;
    if (tid < 192) {
        const int d = tid % HD;
        const int ch = tid / HD;
        float a = 0.f;
        #pragma unroll 4
        for (int i = ch; i < KSEL; i += 4)
            a = fmaf(wl[i], __ldg(&Vb[(size_t)ml[i] * HD + d]), a);
        accs2[ch][d] = a;
    }
    __syncthreads();

    if (tid < HD) {
        const float Z = fwred[0] + fwred[1] + fwred[2] + fwred[3];
        g_O[qoff + row * HD + tid] =
            (accs2[0][tid] + accs2[1][tid] + accs2[2][tid] + accs2[3][tid]) / Z;
    }
}

// ---------------------------------------------------------------------------
// Kernel 4: output projection, n-tiled, 384 threads.
// ---------------------------------------------------------------------------
__global__ void oproj_kernel(const float* __restrict__ ow,
                             const float* __restrict__ ob,
                             float* __restrict__ out, int N, size_t qoff)
{
    __shared__ float o[TD][TN + 1];
    const int tid  = threadIdx.x;
    const int t    = tid % TD;
    const int half = tid / TD;
    const int nt = N / TN;
    const int n0 = (blockIdx.x % nt) * TN;
    const int b  = blockIdx.x / nt;

    for (int i = tid; i < TD * TN; i += 384) {
        const int j  = i / TD;
        const int td = i % TD;
        const int h = td / HD, d = td % HD;
        o[td][j] = g_O[qoff + (((size_t)b * NH + h) * N + n0 + j) * HD + d];
    }
    __syncthreads();

    const int j0 = half * (TN / 2);
    float acc[TN / 2];
    const float bias = ob[t];
    #pragma unroll
    for (int j = 0; j < TN / 2; ++j) acc[j] = bias;

    for (int j = 0; j < TD; ++j) {
        const float w = ow[j * TD + t];
        #pragma unroll
        for (int jj = 0; jj < TN / 2; ++jj)
            acc[jj] = fmaf(o[j][j0 + jj], w, acc[jj]);
    }

    float4* op = (float4*)(out + ((size_t)b * TD + t) * N + n0 + j0);
    #pragma unroll
    for (int q = 0; q < TN / 8; ++q)
        op[q] = make_float4(acc[4 * q], acc[4 * q + 1], acc[4 * q + 2], acc[4 * q + 3]);
}

// ---------------------------------------------------------------------------
// Launch: 3 levels on 3 streams (fork-join, capture-legal) — R11 structure.
// ---------------------------------------------------------------------------
extern "C" void kernel_launch(void* const* d_in, const int* in_sizes, int n_in,
                              void* d_out, int out_size)
{
    (void)in_sizes; (void)n_in; (void)out_size;

    static cudaStream_t st1 = nullptr, st2 = nullptr;
    static cudaEvent_t evr = nullptr, evd1 = nullptr, evd2 = nullptr;
    static const bool inited = []() {
        cudaStreamCreateWithFlags(&st1, cudaStreamNonBlocking);
        cudaStreamCreateWithFlags(&st2, cudaStreamNonBlocking);
        cudaEventCreateWithFlags(&evr,  cudaEventDisableTiming);
        cudaEventCreateWithFlags(&evd1, cudaEventDisableTiming);
        cudaEventCreateWithFlags(&evd2, cudaEventDisableTiming);
        return true;
    }();
    (void)inited;

    const int    Cs[3]    = {64, 128, 192};
    const int    Hs[3]    = {64, 32, 16};
    const size_t soffs[3] = {0, 134217728, 142606336};
    const size_t qoffs[3] = {0, 1572864, 1966080};
    const size_t ooffs[3] = {0, 1572864, 1966080};
    cudaStream_t strs[3]  = {(cudaStream_t)0, st1, st2};

    // Fork.
    cudaEventRecord(evr, 0);
    cudaStreamWaitEvent(st1, evr, 0);
    cudaStreamWaitEvent(st2, evr, 0);

    for (int l = 0; l < 3; ++l) {
        const int C = Cs[l];
        const int H = Hs[l];
        const int N = H * H;
        const int B = 2;
        cudaStream_t st = strs[l];

        const float* f1 = (const float*)d_in[2 * l + 0];
        const float* f2 = (const float*)d_in[2 * l + 1];
        const int wb = 6 + 8 * l;
        const float* qw = (const float*)d_in[wb + 0];
        const float* qb = (const float*)d_in[wb + 1];
        const float* kw = (const float*)d_in[wb + 2];
        const float* kb = (const float*)d_in[wb + 3];
        const float* vw = (const float*)d_in[wb + 4];
        const float* vb = (const float*)d_in[wb + 5];
        const float* ow = (const float*)d_in[wb + 6];
        const float* ob = (const float*)d_in[wb + 7];

        float* outp = (float*)d_out + ooffs[l];

        proj_kernel<<<B * (N / TN), 384, 0, st>>>(f1, f2, qw, qb, kw, kb, vw, vb,
                                                  C, N, H, qoffs[l]);

        dim3 sg(N / 128, N / 128, B * NH);
        scores_kernel<<<sg, 256, 0, st>>>(N, soffs[l], qoffs[l]);

        const size_t ksmem = (size_t)N * sizeof(unsigned int);
        if (l == 0)
            attn_kernel<4, false><<<B * NH * N, 256, ksmem, st>>>(N, soffs[l], qoffs[l]);
        else if (l == 1)
            attn_kernel<1, false><<<B * NH * N, 256, ksmem, st>>>(N, soffs[l], qoffs[l]);
        else
            attn_kernel<1, true><<<B * NH * N, 256, ksmem, st>>>(N, soffs[l], qoffs[l]);

        oproj_kernel<<<B * (N / TN), 384, 0, st>>>(ow, ob, outp, N, qoffs[l]);
    }

    // Join.
    cudaEventRecord(evd1, st1);
    cudaEventRecord(evd2, st2);
    cudaStreamWaitEvent((cudaStream_t)0, evd1, 0);
    cudaStreamWaitEvent((cudaStream_t)0, evd2, 0);
}

// round 14
// speedup vs baseline: 1.5209x; 1.5209x over previous
#include <cuda_runtime.h>
#include <cuda_bf16.h>
#include <cstdint>

// ---------------------------------------------------------------------------
// GlobalMatchingTokenizer: 3 levels of efficient global matching attention.
// B=2, C={64,128,192}, H=W={64,32,16}, N=H*W, TOKEN_DIM=192, NUM_HEADS=4,
// HEAD_DIM=48, TOPK=128.
// Round 14: kernels = R11 (proven 1057us). Level 0 pipelined at head
// granularity: scores per-bh on main stream, attn per-bh on a side stream
// chained by events, so attn(bh) overlaps scores(bh+1).
// ---------------------------------------------------------------------------

#define NH 4
#define HD 48
#define TD 192
#define KSEL 128
#define TN 16
#define CAP 256
#define SPAD 52

// Scratch (device globals; per-level disjoint offsets for stream overlap).
__device__ float g_S[143130624];
__device__ float g_Q[1990656];
__device__ float g_K[1990656];
__device__ float g_V[1990656];
__device__ float g_O[1990656];

// ---------------------------------------------------------------------------
// Kernel 1: QKV projection + positional encoding, n-tiled for weight reuse.
// grid = B*(N/TN), 384 threads.
// ---------------------------------------------------------------------------
__global__ void proj_kernel(const float* __restrict__ f1,
                            const float* __restrict__ f2,
                            const float* __restrict__ qw, const float* __restrict__ qb,
                            const float* __restrict__ kw, const float* __restrict__ kb,
                            const float* __restrict__ vw, const float* __restrict__ vb,
                            int C, int N, int W, size_t qoff)
{
    __shared__ float s1[TD][TN];
    __shared__ float s2[TD][TN];
    const int tid  = threadIdx.x;
    const int t    = tid % TD;
    const int half = tid / TD;
    const int nt = N / TN;
    const int n0 = (blockIdx.x % nt) * TN;
    const int b  = blockIdx.x / nt;

    for (int i = tid; i < C * TN; i += 384) {
        const int c = i / TN, j = i % TN;
        s1[c][j] = f1[((size_t)b * C + c) * N + n0 + j];
        s2[c][j] = f2[((size_t)b * C + c) * N + n0 + j];
    }
    __syncthreads();

    const int j0 = half * (TN / 2);
    float aq[TN / 2], ak[TN / 2], av[TN / 2];
    const float bq = qb[t], bk = kb[t], bv = vb[t];
    #pragma unroll
    for (int j = 0; j < TN / 2; ++j) { aq[j] = bq; ak[j] = bk; av[j] = bv; }

    for (int c = 0; c < C; ++c) {
        const float wq = qw[c * TD + t];
        const float wk = kw[c * TD + t];
        const float wv = vw[c * TD + t];
        #pragma unroll
        for (int j = 0; j < TN / 2; ++j) {
            const float a1 = s1[c][j0 + j];
            const float a2 = s2[c][j0 + j];
            aq[j] = fmaf(a1, wq, aq[j]);
            ak[j] = fmaf(a2, wk, ak[j]);
            av[j] = fmaf(a2, wv, av[j]);
        }
    }

    const float step = -9.210340371976184f / 96.0f;  // -ln(10000)/96
    const float div  = expf(step * (float)(t < 96 ? t : t - 96));
    #pragma unroll
    for (int j = 0; j < TN / 2; ++j) {
        const int n = n0 + j0 + j;
        const float pe = (t < 96) ? sinf((float)(n % W) * div)
                                  : cosf((float)(n / W) * div);
        aq[j] += pe;
        ak[j] += pe;
    }

    const int h = t / HD;
    const int d = t % HD;
    const size_t base = qoff + (((size_t)b * NH + h) * N + n0 + j0) * HD + d;
    #pragma unroll
    for (int j = 0; j < TN / 2; ++j) {
        g_Q[base + (size_t)j * HD] = aq[j];
        g_K[base + (size_t)j * HD] = ak[j];
        g_V[base + (size_t)j * HD] = av[j];
    }
}

// ---------------------------------------------------------------------------
// Kernel 2: scores GEMM (fp32 FFMA). S[bh][n][m] = scale*dot(Q[n],K[m]).
// grid = (N/128, N/128, nz), bh = blockIdx.z + bhoff. 256 thr, 8x8/thread.
// ---------------------------------------------------------------------------
__global__ void __launch_bounds__(256) scores_kernel(int N, size_t soff, size_t qoff,
                                                     int bhoff)
{
    __shared__ float Qs[128][SPAD];
    __shared__ float Ks[128][SPAD];

    const int bh = blockIdx.z + bhoff;
    const float* __restrict__ Qb = g_Q + qoff + (size_t)bh * N * HD;
    const float* __restrict__ Kb = g_K + qoff + (size_t)bh * N * HD;
    float* __restrict__ Sb = g_S + soff + (size_t)bh * N * N;

    const int tid = threadIdx.x;
    const int rb = blockIdx.y * 128;
    const int cb = blockIdx.x * 128;

    for (int i = tid; i < 128 * 12; i += 256) {
        const int r = i / 12, q = (i % 12) * 4;
        *(float4*)&Qs[r][q] = *(const float4*)(Qb + (size_t)(rb + r) * HD + q);
        *(float4*)&Ks[r][q] = *(const float4*)(Kb + (size_t)(cb + r) * HD + q);
    }
    __syncthreads();

    const int ty = tid >> 4, tx = tid & 15;
    float acc[8][8] = {};

    #pragma unroll
    for (int kk = 0; kk < HD; kk += 2) {
        float2 qv[8], kv[8];
        #pragma unroll
        for (int i = 0; i < 8; ++i) {
            qv[i] = *(const float2*)&Qs[ty + 16 * i][kk];
            kv[i] = *(const float2*)&Ks[tx + 16 * i][kk];
        }
        #pragma unroll
        for (int i = 0; i < 8; ++i)
            #pragma unroll
            for (int j = 0; j < 8; ++j) {
                acc[i][j] = fmaf(qv[i].x, kv[j].x, acc[i][j]);
                acc[i][j] = fmaf(qv[i].y, kv[j].y, acc[i][j]);
            }
    }

    const float scale = 0.14433756729740643f;  // 1/sqrt(48)
    #pragma unroll
    for (int i = 0; i < 8; ++i) {
        const size_t ro = (size_t)(rb + ty + 16 * i) * N + cb + tx;
        #pragma unroll
        for (int j = 0; j < 8; ++j)
            Sb[ro + 16 * j] = acc[i][j] * scale;
    }
}

// ---------------------------------------------------------------------------
// Kernel 3: exact top-128 per row (R11 algorithm, rowoff param).
// 256-bin histogram, refinement while bin > CAP; uint4 paths; plain
// predicated atomics; atomic-free Z/V epilogue. 256 threads.
// ---------------------------------------------------------------------------
__device__ __forceinline__ unsigned int floatToKey(float f)
{
    unsigned int u = __float_as_uint(f);
    return (u & 0x80000000u) ? ~u : (u | 0x80000000u);
}
__device__ __forceinline__ float keyToFloat(unsigned int u)
{
    unsigned int b = (u & 0x80000000u) ? (u & 0x7fffffffu) : ~u;
    return __uint_as_float(b);
}

__device__ __forceinline__ void pick_bin(const unsigned int* hist,
                                         int tid, int wid, int lane,
                                         int* wsum, int* s_need,
                                         unsigned int* s_bin, int* s_cand)
{
    const int h = (int)hist[tid];
    int x = h;
    #pragma unroll
    for (int off = 1; off < 32; off <<= 1) {
        const int y = __shfl_down_sync(0xffffffffu, x, off);
        if (lane + off < 32) x += y;
    }
    if (lane == 0) wsum[wid] = x;
    const int need = *s_need;
    __syncthreads();
    int above = x - h;
    for (int w = wid + 1; w < 8; ++w) above += wsum[w];
    if (above < need && above + h >= need) {
        *s_bin  = (unsigned int)tid;
        *s_need = need - above;
        *s_cand = h;
    }
    __syncthreads();
}

template <int CHN, bool GUARD>
__global__ void __launch_bounds__(256) attn_kernel(int N, size_t soff, size_t qoff,
                                                   int rowoff)
{
    extern __shared__ unsigned int keys[];
    __shared__ unsigned int hist[256];
    __shared__ __align__(16) unsigned int ckey[CAP];
    __shared__ int          cidx[CAP];
    __shared__ float        wl[KSEL];
    __shared__ int          ml[KSEL];
    __shared__ float        accs2[4][HD];
    __shared__ int          wsum[8];
    __shared__ unsigned int uwred[8];
    __shared__ float        fwred[4];
    __shared__ int          s_need, s_cand, s_cnt, s_ccnt;
    __shared__ unsigned int s_bin;

    const int tid  = threadIdx.x;
    const int wid  = tid >> 5, lane = tid & 31;
    const size_t row = (size_t)(blockIdx.x + rowoff);
    const float* __restrict__ Srow = g_S + soff + row * (size_t)N;
    const int nv4 = N >> 2;

    hist[tid] = 0u;
    if (tid == 0) { s_need = KSEL; s_cnt = 0; s_ccnt = 0; }
    __syncthreads();

    unsigned int lmax = 0u;
    #pragma unroll
    for (int c = 0; c < CHN; ++c) {
        const int v4 = tid + 256 * c;
        if (!GUARD || v4 < nv4) {
            const float4 f = ((const float4*)Srow)[v4];
            uint4 k;
            k.x = floatToKey(f.x); k.y = floatToKey(f.y);
            k.z = floatToKey(f.z); k.w = floatToKey(f.w);
            ((uint4*)keys)[v4] = k;
            atomicAdd(&hist[k.x >> 24], 1u);
            atomicAdd(&hist[k.y >> 24], 1u);
            atomicAdd(&hist[k.z >> 24], 1u);
            atomicAdd(&hist[k.w >> 24], 1u);
            lmax = max(lmax, max(max(k.x, k.y), max(k.z, k.w)));
        }
    }
    #pragma unroll
    for (int off = 16; off; off >>= 1)
        lmax = max(lmax, __shfl_down_sync(0xffffffffu, lmax, off));
    if (lane == 0) uwred[wid] = lmax;
    __syncthreads();
    unsigned int mk = uwred[0];
    #pragma unroll
    for (int w = 1; w < 8; ++w) mk = max(mk, uwred[w]);
    const float smax = keyToFloat(mk);

    pick_bin(hist, tid, wid, lane, wsum, &s_need, &s_bin, &s_cand);

    int sh = 24;
    unsigned int pfx = s_bin;
    int cand = s_cand;

    while (cand > CAP && sh > 0) {
        const int nsh = sh - 8;
        hist[tid] = 0u;
        __syncthreads();
        #pragma unroll
        for (int c = 0; c < CHN; ++c) {
            const int v4 = tid + 256 * c;
            if (!GUARD || v4 < nv4) {
                const uint4 k = ((const uint4*)keys)[v4];
                const unsigned int kk[4] = {k.x, k.y, k.z, k.w};
                #pragma unroll
                for (int e = 0; e < 4; ++e)
                    if ((kk[e] >> sh) == pfx)
                        atomicAdd(&hist[(kk[e] >> nsh) & 255u], 1u);
            }
        }
        __syncthreads();
        pick_bin(hist, tid, wid, lane, wsum, &s_need, &s_bin, &s_cand);
        pfx = (pfx << 8) | s_bin;
        cand = s_cand;
        sh = nsh;
    }

    const int needC = s_need;

    if (cand <= CAP) {
        #pragma unroll
        for (int c = 0; c < CHN; ++c) {
            const int v4 = tid + 256 * c;
            if (!GUARD || v4 < nv4) {
                const uint4 k = ((const uint4*)keys)[v4];
                const unsigned int kk[4] = {k.x, k.y, k.z, k.w};
                #pragma unroll
                for (int e = 0; e < 4; ++e) {
                    const unsigned int ub = kk[e] >> sh;
                    if (ub > pfx) {
                        const int slot = atomicAdd(&s_cnt, 1);
                        wl[slot] = __expf(keyToFloat(kk[e]) - smax);
                        ml[slot] = 4 * v4 + e;
                    } else if (ub == pfx) {
                        const int slot = atomicAdd(&s_ccnt, 1);
                        ckey[slot] = kk[e];
                        cidx[slot] = 4 * v4 + e;
                    }
                }
            }
        }
        __syncthreads();

        const int cc = s_ccnt;
        if (tid < cc) {
            const unsigned int ki = ckey[tid];
            const int idi = cidx[tid];
            int r = 0;
            for (int j0 = 0; j0 < cc; j0 += 4) {
                const uint4 k4 = *(const uint4*)&ckey[j0];
                if (j0 + 0 < cc) { if (k4.x > ki || (k4.x == ki && cidx[j0 + 0] < idi)) ++r; }
                if (j0 + 1 < cc) { if (k4.y > ki || (k4.y == ki && cidx[j0 + 1] < idi)) ++r; }
                if (j0 + 2 < cc) { if (k4.z > ki || (k4.z == ki && cidx[j0 + 2] < idi)) ++r; }
                if (j0 + 3 < cc) { if (k4.w > ki || (k4.w == ki && cidx[j0 + 3] < idi)) ++r; }
            }
            if (r < needC) {
                const int slot = atomicAdd(&s_cnt, 1);
                wl[slot] = __expf(keyToFloat(ki) - smax);
                ml[slot] = idi;
            }
        }
    } else {
        #pragma unroll
        for (int c = 0; c < CHN; ++c) {
            const int v4 = tid + 256 * c;
            if (!GUARD || v4 < nv4) {
                const uint4 k = ((const uint4*)keys)[v4];
                const unsigned int kk[4] = {k.x, k.y, k.z, k.w};
                #pragma unroll
                for (int e = 0; e < 4; ++e) {
                    if (kk[e] > pfx) {
                        const int slot = atomicAdd(&s_cnt, 1);
                        wl[slot] = __expf(keyToFloat(kk[e]) - smax);
                        ml[slot] = 4 * v4 + e;
                    }
                }
            }
        }
        __syncthreads();
        const int baseCnt = s_cnt;
        const int need = KSEL - baseCnt;
        const float wtie = __expf(keyToFloat(pfx) - smax);
        #pragma unroll
        for (int c = 0; c < CHN; ++c) {
            const int v4 = tid + 256 * c;
            if (!GUARD || v4 < nv4) {
                const uint4 k = ((const uint4*)keys)[v4];
                const unsigned int kk[4] = {k.x, k.y, k.z, k.w};
                #pragma unroll
                for (int e = 0; e < 4; ++e) {
                    if (kk[e] == pfx) {
                        const int idx = 4 * v4 + e;
                        int r = 0;
                        for (int j = 0; j < idx && r < need; ++j)
                            r += (keys[j] == pfx);
                        if (r < need) {
                            wl[baseCnt + r] = wtie;
                            ml[baseCnt + r] = idx;
                        }
                    }
                }
            }
        }
    }
    __syncthreads();

    float z = (tid < KSEL) ? wl[tid] : 0.f;
    #pragma unroll
    for (int off = 16; off; off >>= 1)
        z += __shfl_down_sync(0xffffffffu, z, off);
    if (lane == 0 && wid < 4) fwred[wid] = z;

    const size_t bh = row / (size_t)N;
    const float* __restrict__ Vb = g_V + qoff + bh * (size_t)N * HD;
    if (tid < 192) {
        const int d = tid % HD;
        const int ch = tid / HD;
        float a = 0.f;
        #pragma unroll 4
        for (int i = ch; i < KSEL; i += 4)
            a = fmaf(wl[i], __ldg(&Vb[(size_t)ml[i] * HD + d]), a);
        accs2[ch][d] = a;
    }
    __syncthreads();

    if (tid < HD) {
        const float Z = fwred[0] + fwred[1] + fwred[2] + fwred[3];
        g_O[qoff + row * HD + tid] =
            (accs2[0][tid] + accs2[1][tid] + accs2[2][tid] + accs2[3][tid]) / Z;
    }
}

// ---------------------------------------------------------------------------
// Kernel 4: output projection, n-tiled, 384 threads.
// ---------------------------------------------------------------------------
__global__ void oproj_kernel(const float* __restrict__ ow,
                             const float* __restrict__ ob,
                             float* __restrict__ out, int N, size_t qoff)
{
    __shared__ float o[TD][TN + 1];
    const int tid  = threadIdx.x;
    const int t    = tid % TD;
    const int half = tid / TD;
    const int nt = N / TN;
    const int n0 = (blockIdx.x % nt) * TN;
    const int b  = blockIdx.x / nt;

    for (int i = tid; i < TD * TN; i += 384) {
        const int j  = i / TD;
        const int td = i % TD;
        const int h = td / HD, d = td % HD;
        o[td][j] = g_O[qoff + (((size_t)b * NH + h) * N + n0 + j) * HD + d];
    }
    __syncthreads();

    const int j0 = half * (TN / 2);
    float acc[TN / 2];
    const float bias = ob[t];
    #pragma unroll
    for (int j = 0; j < TN / 2; ++j) acc[j] = bias;

    for (int j = 0; j < TD; ++j) {
        const float w = ow[j * TD + t];
        #pragma unroll
        for (int jj = 0; jj < TN / 2; ++jj)
            acc[jj] = fmaf(o[j][j0 + jj], w, acc[jj]);
    }

    float4* op = (float4*)(out + ((size_t)b * TD + t) * N + n0 + j0);
    #pragma unroll
    for (int q = 0; q < TN / 8; ++q)
        op[q] = make_float4(acc[4 * q], acc[4 * q + 1], acc[4 * q + 2], acc[4 * q + 3]);
}

// ---------------------------------------------------------------------------
// Launch: level 0 pipelined per-head across main stream (scores) and a side
// stream (attn), chained with events. Levels 1-2 whole on own streams.
// ---------------------------------------------------------------------------
extern "C" void kernel_launch(void* const* d_in, const int* in_sizes, int n_in,
                              void* d_out, int out_size)
{
    (void)in_sizes; (void)n_in; (void)out_size;

    static cudaStream_t st1 = nullptr, st2 = nullptr, stA = nullptr;
    static cudaEvent_t evr = nullptr, evd1 = nullptr, evd2 = nullptr, evdA = nullptr;
    static cudaEvent_t evp[8];
    static const bool inited = []() {
        cudaStreamCreateWithFlags(&st1, cudaStreamNonBlocking);
        cudaStreamCreateWithFlags(&st2, cudaStreamNonBlocking);
        cudaStreamCreateWithFlags(&stA, cudaStreamNonBlocking);
        cudaEventCreateWithFlags(&evr,  cudaEventDisableTiming);
        cudaEventCreateWithFlags(&evd1, cudaEventDisableTiming);
        cudaEventCreateWithFlags(&evd2, cudaEventDisableTiming);
        cudaEventCreateWithFlags(&evdA, cudaEventDisableTiming);
        for (int i = 0; i < 8; ++i)
            cudaEventCreateWithFlags(&evp[i], cudaEventDisableTiming);
        return true;
    }();
    (void)inited;

    const int    Cs[3]    = {64, 128, 192};
    const int    Hs[3]    = {64, 32, 16};
    const size_t soffs[3] = {0, 134217728, 142606336};
    const size_t qoffs[3] = {0, 1572864, 1966080};
    const size_t ooffs[3] = {0, 1572864, 1966080};

    // Fork.
    cudaEventRecord(evr, 0);
    cudaStreamWaitEvent(st1, evr, 0);
    cudaStreamWaitEvent(st2, evr, 0);
    cudaStreamWaitEvent(stA, evr, 0);

    // ---- Level 0: pipelined per head ----
    {
        const int l = 0;
        const int C = Cs[l], H = Hs[l], N = H * H, B = 2;
        const float* f1 = (const float*)d_in[0];
        const float* f2 = (const float*)d_in[1];
        const float* qw = (const float*)d_in[6];
        const float* qb = (const float*)d_in[7];
        const float* kw = (const float*)d_in[8];
        const float* kb = (const float*)d_in[9];
        const float* vw = (const float*)d_in[10];
        const float* vb = (const float*)d_in[11];
        const float* ow = (const float*)d_in[12];
        const float* ob = (const float*)d_in[13];
        float* outp = (float*)d_out + ooffs[l];
        const size_t ksmem = (size_t)N * sizeof(unsigned int);

        proj_kernel<<<B * (N / TN), 384>>>(f1, f2, qw, qb, kw, kb, vw, vb,
                                           C, N, H, qoffs[l]);

        const dim3 sg(N / 128, N / 128, 1);
        for (int bh = 0; bh < B * NH; ++bh) {
            scores_kernel<<<sg, 256>>>(N, soffs[l], qoffs[l], bh);
            cudaEventRecord(evp[bh], 0);
            cudaStreamWaitEvent(stA, evp[bh], 0);
            attn_kernel<4, false><<<N, 256, ksmem, stA>>>(N, soffs[l], qoffs[l], bh * N);
        }
        cudaEventRecord(evdA, stA);
        cudaStreamWaitEvent((cudaStream_t)0, evdA, 0);
        oproj_kernel<<<B * (N / TN), 384>>>(ow, ob, outp, N, qoffs[l]);
    }

    // ---- Levels 1, 2: whole, on own streams ----
    for (int l = 1; l < 3; ++l) {
        const int C = Cs[l], H = Hs[l], N = H * H, B = 2;
        cudaStream_t st = (l == 1) ? st1 : st2;

        const float* f1 = (const float*)d_in[2 * l + 0];
        const float* f2 = (const float*)d_in[2 * l + 1];
        const int wb = 6 + 8 * l;
        const float* qw = (const float*)d_in[wb + 0];
        const float* qb = (const float*)d_in[wb + 1];
        const float* kw = (const float*)d_in[wb + 2];
        const float* kb = (const float*)d_in[wb + 3];
        const float* vw = (const float*)d_in[wb + 4];
        const float* vb = (const float*)d_in[wb + 5];
        const float* ow = (const float*)d_in[wb + 6];
        const float* ob = (const float*)d_in[wb + 7];

        float* outp = (float*)d_out + ooffs[l];
        const size_t ksmem = (size_t)N * sizeof(unsigned int);

        proj_kernel<<<B * (N / TN), 384, 0, st>>>(f1, f2, qw, qb, kw, kb, vw, vb,
                                                  C, N, H, qoffs[l]);
        dim3 sg(N / 128, N / 128, B * NH);
        scores_kernel<<<sg, 256, 0, st>>>(N, soffs[l], qoffs[l], 0);
        if (l == 1)
            attn_kernel<1, false><<<B * NH * N, 256, ksmem, st>>>(N, soffs[l], qoffs[l], 0);
        else
            attn_kernel<1, true><<<B * NH * N, 256, ksmem, st>>>(N, soffs[l], qoffs[l], 0);
        oproj_kernel<<<B * (N / TN), 384, 0, st>>>(ow, ob, outp, N, qoffs[l]);
    }

    // Join.
    cudaEventRecord(evd1, st1);
    cudaEventRecord(evd2, st2);
    cudaStreamWaitEvent((cudaStream_t)0, evd1, 0);
    cudaStreamWaitEvent((cudaStream_t)0, evd2, 0);
}

// round 15
// speedup vs baseline: 1.7697x; 1.1636x over previous
#include <cuda_runtime.h>
#include <cuda_bf16.h>
#include <cstdint>

// ---------------------------------------------------------------------------
// GlobalMatchingTokenizer: 3 levels of efficient global matching attention.
// B=2, C={64,128,192}, H=W={64,32,16}, N=H*W, TOKEN_DIM=192, NUM_HEADS=4,
// HEAD_DIM=48, TOPK=128.
// Round 15: R11 launch structure + attn. scores fixed for occupancy:
// ncu showed regs=202 -> 1 CTA/SM, issue 45%. Now __launch_bounds__(256,2),
// scalar fragments, partial unroll -> 2 CTAs/SM.
// ---------------------------------------------------------------------------

#define NH 4
#define HD 48
#define TD 192
#define KSEL 128
#define TN 16
#define CAP 256
#define SPAD 52

// Scratch (device globals; per-level disjoint offsets for stream overlap).
__device__ float g_S[143130624];
__device__ float g_Q[1990656];
__device__ float g_K[1990656];
__device__ float g_V[1990656];
__device__ float g_O[1990656];

// ---------------------------------------------------------------------------
// Kernel 1: QKV projection + positional encoding, n-tiled for weight reuse.
// grid = B*(N/TN), 384 threads.
// ---------------------------------------------------------------------------
__global__ void proj_kernel(const float* __restrict__ f1,
                            const float* __restrict__ f2,
                            const float* __restrict__ qw, const float* __restrict__ qb,
                            const float* __restrict__ kw, const float* __restrict__ kb,
                            const float* __restrict__ vw, const float* __restrict__ vb,
                            int C, int N, int W, size_t qoff)
{
    __shared__ float s1[TD][TN];
    __shared__ float s2[TD][TN];
    const int tid  = threadIdx.x;
    const int t    = tid % TD;
    const int half = tid / TD;
    const int nt = N / TN;
    const int n0 = (blockIdx.x % nt) * TN;
    const int b  = blockIdx.x / nt;

    for (int i = tid; i < C * TN; i += 384) {
        const int c = i / TN, j = i % TN;
        s1[c][j] = f1[((size_t)b * C + c) * N + n0 + j];
        s2[c][j] = f2[((size_t)b * C + c) * N + n0 + j];
    }
    __syncthreads();

    const int j0 = half * (TN / 2);
    float aq[TN / 2], ak[TN / 2], av[TN / 2];
    const float bq = qb[t], bk = kb[t], bv = vb[t];
    #pragma unroll
    for (int j = 0; j < TN / 2; ++j) { aq[j] = bq; ak[j] = bk; av[j] = bv; }

    for (int c = 0; c < C; ++c) {
        const float wq = qw[c * TD + t];
        const float wk = kw[c * TD + t];
        const float wv = vw[c * TD + t];
        #pragma unroll
        for (int j = 0; j < TN / 2; ++j) {
            const float a1 = s1[c][j0 + j];
            const float a2 = s2[c][j0 + j];
            aq[j] = fmaf(a1, wq, aq[j]);
            ak[j] = fmaf(a2, wk, ak[j]);
            av[j] = fmaf(a2, wv, av[j]);
        }
    }

    const float step = -9.210340371976184f / 96.0f;  // -ln(10000)/96
    const float div  = expf(step * (float)(t < 96 ? t : t - 96));
    #pragma unroll
    for (int j = 0; j < TN / 2; ++j) {
        const int n = n0 + j0 + j;
        const float pe = (t < 96) ? sinf((float)(n % W) * div)
                                  : cosf((float)(n / W) * div);
        aq[j] += pe;
        ak[j] += pe;
    }

    const int h = t / HD;
    const int d = t % HD;
    const size_t base = qoff + (((size_t)b * NH + h) * N + n0 + j0) * HD + d;
    #pragma unroll
    for (int j = 0; j < TN / 2; ++j) {
        g_Q[base + (size_t)j * HD] = aq[j];
        g_K[base + (size_t)j * HD] = ak[j];
        g_V[base + (size_t)j * HD] = av[j];
    }
}

// ---------------------------------------------------------------------------
// Kernel 2: scores GEMM (fp32 FFMA). S[bh][n][m] = scale*dot(Q[n],K[m]).
// grid = (N/128, N/128, B*NH), 256 threads, 8x8 per thread, interleaved.
// __launch_bounds__(256, 2): cap regs at 128 so 2 CTAs/SM are resident
// (ncu showed 202 regs -> 1 CTA/SM -> issue 45%). Scalar fragments.
// ---------------------------------------------------------------------------
__global__ void __launch_bounds__(256, 2) scores_kernel(int N, size_t soff, size_t qoff)
{
    __shared__ float Qs[128][SPAD];
    __shared__ float Ks[128][SPAD];

    const int bh = blockIdx.z;
    const float* __restrict__ Qb = g_Q + qoff + (size_t)bh * N * HD;
    const float* __restrict__ Kb = g_K + qoff + (size_t)bh * N * HD;
    float* __restrict__ Sb = g_S + soff + (size_t)bh * N * N;

    const int tid = threadIdx.x;
    const int rb = blockIdx.y * 128;
    const int cb = blockIdx.x * 128;

    for (int i = tid; i < 128 * 12; i += 256) {
        const int r = i / 12, q = (i % 12) * 4;
        *(float4*)&Qs[r][q] = *(const float4*)(Qb + (size_t)(rb + r) * HD + q);
        *(float4*)&Ks[r][q] = *(const float4*)(Kb + (size_t)(cb + r) * HD + q);
    }
    __syncthreads();

    const int ty = tid >> 4, tx = tid & 15;
    float acc[8][8] = {};

    #pragma unroll 4
    for (int kk = 0; kk < HD; ++kk) {
        float qv[8], kv[8];
        #pragma unroll
        for (int i = 0; i < 8; ++i) {
            qv[i] = Qs[ty + 16 * i][kk];
            kv[i] = Ks[tx + 16 * i][kk];
        }
        #pragma unroll
        for (int i = 0; i < 8; ++i)
            #pragma unroll
            for (int j = 0; j < 8; ++j)
                acc[i][j] = fmaf(qv[i], kv[j], acc[i][j]);
    }

    const float scale = 0.14433756729740643f;  // 1/sqrt(48)
    #pragma unroll
    for (int i = 0; i < 8; ++i) {
        const size_t ro = (size_t)(rb + ty + 16 * i) * N + cb + tx;
        #pragma unroll
        for (int j = 0; j < 8; ++j)
            Sb[ro + 16 * j] = acc[i][j] * scale;
    }
}

// ---------------------------------------------------------------------------
// Kernel 3: exact top-128 per row (R11 algorithm, unchanged).
// ---------------------------------------------------------------------------
__device__ __forceinline__ unsigned int floatToKey(float f)
{
    unsigned int u = __float_as_uint(f);
    return (u & 0x80000000u) ? ~u : (u | 0x80000000u);
}
__device__ __forceinline__ float keyToFloat(unsigned int u)
{
    unsigned int b = (u & 0x80000000u) ? (u & 0x7fffffffu) : ~u;
    return __uint_as_float(b);
}

__device__ __forceinline__ void pick_bin(const unsigned int* hist,
                                         int tid, int wid, int lane,
                                         int* wsum, int* s_need,
                                         unsigned int* s_bin, int* s_cand)
{
    const int h = (int)hist[tid];
    int x = h;
    #pragma unroll
    for (int off = 1; off < 32; off <<= 1) {
        const int y = __shfl_down_sync(0xffffffffu, x, off);
        if (lane + off < 32) x += y;
    }
    if (lane == 0) wsum[wid] = x;
    const int need = *s_need;
    __syncthreads();
    int above = x - h;
    for (int w = wid + 1; w < 8; ++w) above += wsum[w];
    if (above < need && above + h >= need) {
        *s_bin  = (unsigned int)tid;
        *s_need = need - above;
        *s_cand = h;
    }
    __syncthreads();
}

template <int CHN, bool GUARD>
__global__ void __launch_bounds__(256) attn_kernel(int N, size_t soff, size_t qoff)
{
    extern __shared__ unsigned int keys[];
    __shared__ unsigned int hist[256];
    __shared__ __align__(16) unsigned int ckey[CAP];
    __shared__ int          cidx[CAP];
    __shared__ float        wl[KSEL];
    __shared__ int          ml[KSEL];
    __shared__ float        accs2[4][HD];
    __shared__ int          wsum[8];
    __shared__ unsigned int uwred[8];
    __shared__ float        fwred[4];
    __shared__ int          s_need, s_cand, s_cnt, s_ccnt;
    __shared__ unsigned int s_bin;

    const int tid  = threadIdx.x;
    const int wid  = tid >> 5, lane = tid & 31;
    const size_t row = blockIdx.x;
    const float* __restrict__ Srow = g_S + soff + row * (size_t)N;
    const int nv4 = N >> 2;

    hist[tid] = 0u;
    if (tid == 0) { s_need = KSEL; s_cnt = 0; s_ccnt = 0; }
    __syncthreads();

    unsigned int lmax = 0u;
    #pragma unroll
    for (int c = 0; c < CHN; ++c) {
        const int v4 = tid + 256 * c;
        if (!GUARD || v4 < nv4) {
            const float4 f = ((const float4*)Srow)[v4];
            uint4 k;
            k.x = floatToKey(f.x); k.y = floatToKey(f.y);
            k.z = floatToKey(f.z); k.w = floatToKey(f.w);
            ((uint4*)keys)[v4] = k;
            atomicAdd(&hist[k.x >> 24], 1u);
            atomicAdd(&hist[k.y >> 24], 1u);
            atomicAdd(&hist[k.z >> 24], 1u);
            atomicAdd(&hist[k.w >> 24], 1u);
            lmax = max(lmax, max(max(k.x, k.y), max(k.z, k.w)));
        }
    }
    #pragma unroll
    for (int off = 16; off; off >>= 1)
        lmax = max(lmax, __shfl_down_sync(0xffffffffu, lmax, off));
    if (lane == 0) uwred[wid] = lmax;
    __syncthreads();
    unsigned int mk = uwred[0];
    #pragma unroll
    for (int w = 1; w < 8; ++w) mk = max(mk, uwred[w]);
    const float smax = keyToFloat(mk);

    pick_bin(hist, tid, wid, lane, wsum, &s_need, &s_bin, &s_cand);

    int sh = 24;
    unsigned int pfx = s_bin;
    int cand = s_cand;

    while (cand > CAP && sh > 0) {
        const int nsh = sh - 8;
        hist[tid] = 0u;
        __syncthreads();
        #pragma unroll
        for (int c = 0; c < CHN; ++c) {
            const int v4 = tid + 256 * c;
            if (!GUARD || v4 < nv4) {
                const uint4 k = ((const uint4*)keys)[v4];
                const unsigned int kk[4] = {k.x, k.y, k.z, k.w};
                #pragma unroll
                for (int e = 0; e < 4; ++e)
                    if ((kk[e] >> sh) == pfx)
                        atomicAdd(&hist[(kk[e] >> nsh) & 255u], 1u);
            }
        }
        __syncthreads();
        pick_bin(hist, tid, wid, lane, wsum, &s_need, &s_bin, &s_cand);
        pfx = (pfx << 8) | s_bin;
        cand = s_cand;
        sh = nsh;
    }

    const int needC = s_need;

    if (cand <= CAP) {
        #pragma unroll
        for (int c = 0; c < CHN; ++c) {
            const int v4 = tid + 256 * c;
            if (!GUARD || v4 < nv4) {
                const uint4 k = ((const uint4*)keys)[v4];
                const unsigned int kk[4] = {k.x, k.y, k.z, k.w};
                #pragma unroll
                for (int e = 0; e < 4; ++e) {
                    const unsigned int ub = kk[e] >> sh;
                    if (ub > pfx) {
                        const int slot = atomicAdd(&s_cnt, 1);
                        wl[slot] = __expf(keyToFloat(kk[e]) - smax);
                        ml[slot] = 4 * v4 + e;
                    } else if (ub == pfx) {
                        const int slot = atomicAdd(&s_ccnt, 1);
                        ckey[slot] = kk[e];
                        cidx[slot] = 4 * v4 + e;
                    }
                }
            }
        }
        __syncthreads();

        const int cc = s_ccnt;
        if (tid < cc) {
            const unsigned int ki = ckey[tid];
            const int idi = cidx[tid];
            int r = 0;
            for (int j0 = 0; j0 < cc; j0 += 4) {
                const uint4 k4 = *(const uint4*)&ckey[j0];
                if (j0 + 0 < cc) { if (k4.x > ki || (k4.x == ki && cidx[j0 + 0] < idi)) ++r; }
                if (j0 + 1 < cc) { if (k4.y > ki || (k4.y == ki && cidx[j0 + 1] < idi)) ++r; }
                if (j0 + 2 < cc) { if (k4.z > ki || (k4.z == ki && cidx[j0 + 2] < idi)) ++r; }
                if (j0 + 3 < cc) { if (k4.w > ki || (k4.w == ki && cidx[j0 + 3] < idi)) ++r; }
            }
            if (r < needC) {
                const int slot = atomicAdd(&s_cnt, 1);
                wl[slot] = __expf(keyToFloat(ki) - smax);
                ml[slot] = idi;
            }
        }
    } else {
        #pragma unroll
        for (int c = 0; c < CHN; ++c) {
            const int v4 = tid + 256 * c;
            if (!GUARD || v4 < nv4) {
                const uint4 k = ((const uint4*)keys)[v4];
                const unsigned int kk[4] = {k.x, k.y, k.z, k.w};
                #pragma unroll
                for (int e = 0; e < 4; ++e) {
                    if (kk[e] > pfx) {
                        const int slot = atomicAdd(&s_cnt, 1);
                        wl[slot] = __expf(keyToFloat(kk[e]) - smax);
                        ml[slot] = 4 * v4 + e;
                    }
                }
            }
        }
        __syncthreads();
        const int baseCnt = s_cnt;
        const int need = KSEL - baseCnt;
        const float wtie = __expf(keyToFloat(pfx) - smax);
        #pragma unroll
        for (int c = 0; c < CHN; ++c) {
            const int v4 = tid + 256 * c;
            if (!GUARD || v4 < nv4) {
                const uint4 k = ((const uint4*)keys)[v4];
                const unsigned int kk[4] = {k.x, k.y, k.z, k.w};
                #pragma unroll
                for (int e = 0; e < 4; ++e) {
                    if (kk[e] == pfx) {
                        const int idx = 4 * v4 + e;
                        int r = 0;
                        for (int j = 0; j < idx && r < need; ++j)
                            r += (keys[j] == pfx);
                        if (r < need) {
                            wl[baseCnt + r] = wtie;
                            ml[baseCnt + r] = idx;
                        }
                    }
                }
            }
        }
    }
    __syncthreads();

    float z = (tid < KSEL) ? wl[tid] : 0.f;
    #pragma unroll
    for (int off = 16; off; off >>= 1)
        z += __shfl_down_sync(0xffffffffu, z, off);
    if (lane == 0 && wid < 4) fwred[wid] = z;

    const size_t bh = row / (size_t)N;
    const float* __restrict__ Vb = g_V + qoff + bh * (size_t)N * HD;
    if (tid < 192) {
        const int d = tid % HD;
        const int ch = tid / HD;
        float a = 0.f;
        #pragma unroll 4
        for (int i = ch; i < KSEL; i += 4)
            a = fmaf(wl[i], __ldg(&Vb[(size_t)ml[i] * HD + d]), a);
        accs2[ch][d] = a;
    }
    __syncthreads();

    if (tid < HD) {
        const float Z = fwred[0] + fwred[1] + fwred[2] + fwred[3];
        g_O[qoff + row * HD + tid] =
            (accs2[0][tid] + accs2[1][tid] + accs2[2][tid] + accs2[3][tid]) / Z;
    }
}

// ---------------------------------------------------------------------------
// Kernel 4: output projection, n-tiled, 384 threads.
// ---------------------------------------------------------------------------
__global__ void oproj_kernel(const float* __restrict__ ow,
                             const float* __restrict__ ob,
                             float* __restrict__ out, int N, size_t qoff)
{
    __shared__ float o[TD][TN + 1];
    const int tid  = threadIdx.x;
    const int t    = tid % TD;
    const int half = tid / TD;
    const int nt = N / TN;
    const int n0 = (blockIdx.x % nt) * TN;
    const int b  = blockIdx.x / nt;

    for (int i = tid; i < TD * TN; i += 384) {
        const int j  = i / TD;
        const int td = i % TD;
        const int h = td / HD, d = td % HD;
        o[td][j] = g_O[qoff + (((size_t)b * NH + h) * N + n0 + j) * HD + d];
    }
    __syncthreads();

    const int j0 = half * (TN / 2);
    float acc[TN / 2];
    const float bias = ob[t];
    #pragma unroll
    for (int j = 0; j < TN / 2; ++j) acc[j] = bias;

    for (int j = 0; j < TD; ++j) {
        const float w = ow[j * TD + t];
        #pragma unroll
        for (int jj = 0; jj < TN / 2; ++jj)
            acc[jj] = fmaf(o[j][j0 + jj], w, acc[jj]);
    }

    float4* op = (float4*)(out + ((size_t)b * TD + t) * N + n0 + j0);
    #pragma unroll
    for (int q = 0; q < TN / 8; ++q)
        op[q] = make_float4(acc[4 * q], acc[4 * q + 1], acc[4 * q + 2], acc[4 * q + 3]);
}

// ---------------------------------------------------------------------------
// Launch: 3 levels on 3 streams (fork-join, capture-legal) — R11 structure.
// ---------------------------------------------------------------------------
extern "C" void kernel_launch(void* const* d_in, const int* in_sizes, int n_in,
                              void* d_out, int out_size)
{
    (void)in_sizes; (void)n_in; (void)out_size;

    static cudaStream_t st1 = nullptr, st2 = nullptr;
    static cudaEvent_t evr = nullptr, evd1 = nullptr, evd2 = nullptr;
    static const bool inited = []() {
        cudaStreamCreateWithFlags(&st1, cudaStreamNonBlocking);
        cudaStreamCreateWithFlags(&st2, cudaStreamNonBlocking);
        cudaEventCreateWithFlags(&evr,  cudaEventDisableTiming);
        cudaEventCreateWithFlags(&evd1, cudaEventDisableTiming);
        cudaEventCreateWithFlags(&evd2, cudaEventDisableTiming);
        return true;
    }();
    (void)inited;

    const int    Cs[3]    = {64, 128, 192};
    const int    Hs[3]    = {64, 32, 16};
    const size_t soffs[3] = {0, 134217728, 142606336};
    const size_t qoffs[3] = {0, 1572864, 1966080};
    const size_t ooffs[3] = {0, 1572864, 1966080};
    cudaStream_t strs[3]  = {(cudaStream_t)0, st1, st2};

    // Fork.
    cudaEventRecord(evr, 0);
    cudaStreamWaitEvent(st1, evr, 0);
    cudaStreamWaitEvent(st2, evr, 0);

    for (int l = 0; l < 3; ++l) {
        const int C = Cs[l];
        const int H = Hs[l];
        const int N = H * H;
        const int B = 2;
        cudaStream_t st = strs[l];

        const float* f1 = (const float*)d_in[2 * l + 0];
        const float* f2 = (const float*)d_in[2 * l + 1];
        const int wb = 6 + 8 * l;
        const float* qw = (const float*)d_in[wb + 0];
        const float* qb = (const float*)d_in[wb + 1];
        const float* kw = (const float*)d_in[wb + 2];
        const float* kb = (const float*)d_in[wb + 3];
        const float* vw = (const float*)d_in[wb + 4];
        const float* vb = (const float*)d_in[wb + 5];
        const float* ow = (const float*)d_in[wb + 6];
        const float* ob = (const float*)d_in[wb + 7];

        float* outp = (float*)d_out + ooffs[l];

        proj_kernel<<<B * (N / TN), 384, 0, st>>>(f1, f2, qw, qb, kw, kb, vw, vb,
                                                  C, N, H, qoffs[l]);

        dim3 sg(N / 128, N / 128, B * NH);
        scores_kernel<<<sg, 256, 0, st>>>(N, soffs[l], qoffs[l]);

        const size_t ksmem = (size_t)N * sizeof(unsigned int);
        if (l == 0)
            attn_kernel<4, false><<<B * NH * N, 256, ksmem, st>>>(N, soffs[l], qoffs[l]);
        else if (l == 1)
            attn_kernel<1, false><<<B * NH * N, 256, ksmem, st>>>(N, soffs[l], qoffs[l]);
        else
            attn_kernel<1, true><<<B * NH * N, 256, ksmem, st>>>(N, soffs[l], qoffs[l]);

        oproj_kernel<<<B * (N / TN), 384, 0, st>>>(ow, ob, outp, N, qoffs[l]);
    }

    // Join.
    cudaEventRecord(evd1, st1);
    cudaEventRecord(evd2, st2);
    cudaStreamWaitEvent((cudaStream_t)0, evd1, 0);
    cudaStreamWaitEvent((cudaStream_t)0, evd2, 0);
}